// round 14
// baseline (speedup 1.0000x reference)
#include <cuda_runtime.h>
#include <cuda_fp16.h>
#include <cstdint>
#include <math.h>

// out = GELU_exact(x @ W.T + b)
// R14: fp16 single-term mma.sync GEMM with x->fp16 conversion FUSED into the
// GEMM stage loader (no x pack kernel): per kt each thread LDG.128s its 128B
// f32 slice of the kt+2 A tile, converts (F2FP rne), STS.128s into the
// swizzled smem stage. B stays on the cp.async ring from pre-packed fp16 W.
// Tile 128x128, 8 warps (warp 64x32), occ 2, 3-stage ring, B-frag double buffer.

#define NN 8192
#define KK 512
#define OO 512

#define BM 128
#define BN 128
#define BK 64                    // k per tile (f16 rows: 128 B)
#define NKT (KK / BK)            // 8
#define THREADS 256

#define ST_B   16384
#define STAGE  32768
#define NSTAGE 3
#define SMEM_TOTAL (NSTAGE * STAGE)   // 96 KB

__device__ __align__(128) __half g_wh[OO * KK];   // 0.5 MB packed W

__device__ __forceinline__ uint32_t smem_u32(const void* p) {
    uint32_t a;
    asm("{ .reg .u64 t; cvta.to.shared.u64 t, %1; cvt.u32.u64 %0, t; }" : "=r"(a) : "l"(p));
    return a;
}

#define CP16(dst, src) \
    asm volatile("cp.async.cg.shared.global [%0], [%1], 16;" :: "r"(dst), "l"(src) : "memory")
#define CP_COMMIT() asm volatile("cp.async.commit_group;" ::: "memory")
#define CP_WAIT1()  asm volatile("cp.async.wait_group 1;" ::: "memory")

#define STS128(addr, v) \
    asm volatile("st.shared.v4.b32 [%0], {%1,%2,%3,%4};" \
                 :: "r"(addr), "r"((v).x), "r"((v).y), "r"((v).z), "r"((v).w) : "memory")

__device__ __forceinline__ void ldm4(uint32_t* r, uint32_t addr) {
    asm volatile("ldmatrix.sync.aligned.m8n8.x4.shared.b16 {%0,%1,%2,%3}, [%4];"
                 : "=r"(r[0]), "=r"(r[1]), "=r"(r[2]), "=r"(r[3]) : "r"(addr));
}

__device__ __forceinline__ void mma_f16(float* d, const uint32_t* a, const uint32_t* b) {
    asm volatile(
        "mma.sync.aligned.m16n8k16.row.col.f32.f16.f16.f32 "
        "{%0,%1,%2,%3}, {%4,%5,%6,%7}, {%8,%9}, {%0,%1,%2,%3};"
        : "+f"(d[0]), "+f"(d[1]), "+f"(d[2]), "+f"(d[3])
        : "r"(a[0]), "r"(a[1]), "r"(a[2]), "r"(a[3]), "r"(b[0]), "r"(b[1]));
}

__device__ __forceinline__ uint32_t packh2(float a, float b) {
    __half2 h = __floats2half2_rn(a, b);
    return *(uint32_t*)&h;
}

// swizzled byte offset in a 128B-row tile: row r, 16B-chunk c (0..7)
__device__ __forceinline__ uint32_t swz8(int r, int c) {
    return (uint32_t)(r * 128 + (((c ^ (r & 7))) << 4));
}

// A&S 7.1.26 erf (abs err 1.5e-7)
__device__ __forceinline__ float gelu_f(float h) {
    float s = h * 0.70710678118654752f;
    float a = fabsf(s);
    float t = __frcp_rn(fmaf(0.3275911f, a, 1.0f));
    float p = fmaf(fmaf(fmaf(fmaf(1.061405429f, t, -1.453152027f), t, 1.421413741f),
                        t, -0.284496736f), t, 0.254829592f) * t;
    float e = __expf(-a * a);
    float erfv = fmaf(-p, e, 1.0f);
    erfv = copysignf(erfv, s);
    return 0.5f * h * (1.0f + erfv);
}

// ---------------- W pack kernel: f32 -> fp16 (rne), 0.5 MB ----------------
__global__ __launch_bounds__(256) void packw_kernel(const float* __restrict__ W) {
    const int g = blockIdx.x * 256 + threadIdx.x;   // 32768 groups of 8
    const float* src = W + (size_t)g * 8;
    __half* dst = g_wh + (size_t)g * 8;
    float4 v0 = *(const float4*)src;
    float4 v1 = *(const float4*)(src + 4);
    uint4 o;
    o.x = packh2(v0.x, v0.y);
    o.y = packh2(v0.z, v0.w);
    o.z = packh2(v1.x, v1.y);
    o.w = packh2(v1.z, v1.w);
    *(uint4*)dst = o;
}

// convert one 4-float4 batch (16 f32 -> 8 h2 -> 2 STS.128)
__device__ __forceinline__ void cvt_sts_batch(const float4* u, uint32_t aBase, int jb) {
    uint4 p0, p1;
    p0.x = packh2(u[0].x, u[0].y); p0.y = packh2(u[0].z, u[0].w);
    p0.z = packh2(u[1].x, u[1].y); p0.w = packh2(u[1].z, u[1].w);
    p1.x = packh2(u[2].x, u[2].y); p1.y = packh2(u[2].z, u[2].w);
    p1.z = packh2(u[3].x, u[3].y); p1.w = packh2(u[3].z, u[3].w);
    STS128(aBase ^ ((uint32_t)(2 * jb) << 4), p0);
    STS128(aBase ^ ((uint32_t)(2 * jb + 1) << 4), p1);
}

// ---------------- main GEMM kernel ----------------
__global__ __launch_bounds__(THREADS, 2)
void gemm_f16_kernel(const float* __restrict__ x, const float* __restrict__ bias,
                     float* __restrict__ C) {
    extern __shared__ uint8_t smem[];
    const uint32_t S = smem_u32(smem);
    const int tid = threadIdx.x;
    const int l = tid & 31, wid = tid >> 5;
    const int mwarp = wid & 1;   // 2 M-warps of 64 rows
    const int nwarp = wid >> 1;  // 4 N-warps of 32 cols
    const int mb = blockIdx.x, nb = blockIdx.y;

    // ---- A converter addressing: thread -> (row, k-half) ----
    const int ar = tid >> 1, ah = tid & 1;         // row 0..127, half 0/1
    const float* gx = x + (size_t)(mb * BM + ar) * KK + ah * 32;  // +=64/kt
    const uint32_t aOff = swz8(ar, ah * 4);        // chunk j: ^ (j<<4)

    // ---- B loader (cp.async): 4 chunks/thread/kt ----
    const int lr = tid >> 3, lc = tid & 7;
    const uint8_t* gB0 = (const uint8_t*)(g_wh + (size_t)(nb * BN + lr) * KK + lc * 8);
    const uint32_t dB0 = ST_B + swz8(lr, lc);      // j: smem +4096, gmem +32*KK*2

    // ---- ldmatrix bases ----
    const int a_r = ((l >> 3) & 1) * 8 + (l & 7);
    const int a_cs = (l >> 4) & 1;
    const int b_n = ((l >> 4) & 1) * 8 + (l & 7);
    const int b_cs = (l >> 3) & 1;
    uint32_t baseA[4], baseB[2];
#pragma unroll
    for (int mf = 0; mf < 4; mf++) baseA[mf] = swz8(mwarp * 64 + mf * 16 + a_r, a_cs);
#pragma unroll
    for (int nf2 = 0; nf2 < 2; nf2++) baseB[nf2] = ST_B + swz8(nwarp * 32 + nf2 * 16 + b_n, b_cs);

    float acc[4][4][4];
#pragma unroll
    for (int i = 0; i < 4; i++)
#pragma unroll
        for (int j = 0; j < 4; j++)
#pragma unroll
            for (int k = 0; k < 4; k++) acc[i][j][k] = 0.0f;

    // ---- prologue: stages 0,1 (A: LDG+cvt+STS, B: cp.async) ----
#pragma unroll
    for (int s = 0; s < 2; s++) {
        const uint32_t st = S + s * STAGE;
        const float* gk = gx + s * 64;
#pragma unroll
        for (int b2 = 0; b2 < 2; b2++) {
            float4 u[4];
#pragma unroll
            for (int j = 0; j < 4; j++) u[j] = __ldg((const float4*)(gk + (b2 * 4 + j) * 4));
            cvt_sts_batch(u, st + aOff, b2);
        }
#pragma unroll
        for (int j = 0; j < 4; j++)
            CP16(st + dB0 + j * 4096, gB0 + (size_t)j * (32 * KK * 2) + s * 128);
        CP_COMMIT();
    }

    for (int kt = 0; kt < NKT; kt++) {
        CP_WAIT1();
        __syncthreads();
        const bool pf = (kt + 2 < NKT);
        const uint32_t st2 = S + ((kt + 2) % NSTAGE) * STAGE;
        if (pf) {
            const uint32_t go = (uint32_t)(kt + 2) * 128;
#pragma unroll
            for (int j = 0; j < 4; j++)
                CP16(st2 + dB0 + j * 4096, gB0 + (size_t)j * (32 * KK * 2) + go);
        }
        CP_COMMIT();   // commit every iter (keeps WAIT1 group bookkeeping exact)

        const uint32_t stg = S + (kt % NSTAGE) * STAGE;
        const float* gk2 = gx + (kt + 2) * 64;

        // A-stage batch 0 LDG (for kt+2) — consumed 2 slices later
        float4 u[4];
        if (pf) {
#pragma unroll
            for (int j = 0; j < 4; j++) u[j] = __ldg((const float4*)(gk2 + j * 4));
        }

        uint32_t Bf[2][8];
#pragma unroll
        for (int nf2 = 0; nf2 < 2; nf2++)
            ldm4(&Bf[0][nf2 * 4], stg + baseB[nf2]);

#pragma unroll
        for (int ks = 0; ks < 4; ks++) {
            const int cur = ks & 1, nxt = cur ^ 1;
            if (ks < 3) {
                const uint32_t nko = (uint32_t)(2 * (ks + 1)) << 4;
#pragma unroll
                for (int nf2 = 0; nf2 < 2; nf2++)
                    ldm4(&Bf[nxt][nf2 * 4], stg + (baseB[nf2] ^ nko));
            }
            const uint32_t ksoff = (uint32_t)(2 * ks) << 4;
#pragma unroll
            for (int mf = 0; mf < 4; mf++) {
                uint32_t A[4];
                ldm4(A, stg + (baseA[mf] ^ ksoff));
#pragma unroll
                for (int nf = 0; nf < 4; nf++)
                    mma_f16(acc[mf][nf], A, &Bf[cur][nf * 2]);
            }
            // mid-loop: drain batch0, fetch batch1; end: drain batch1
            if (pf && ks == 1) {
                cvt_sts_batch(u, st2 + aOff, 0);
#pragma unroll
                for (int j = 0; j < 4; j++) u[j] = __ldg((const float4*)(gk2 + (4 + j) * 4));
            }
            if (pf && ks == 3) cvt_sts_batch(u, st2 + aOff, 1);
        }
    }

    // epilogue: bias + GELU
#pragma unroll
    for (int mf = 0; mf < 4; mf++) {
#pragma unroll
        for (int nf = 0; nf < 4; nf++) {
            int m0 = mb * BM + mwarp * 64 + mf * 16 + (l >> 2);
            int n0 = nb * BN + nwarp * 32 + nf * 8 + 2 * (l & 3);
            float b0 = __ldg(&bias[n0]);
            float b1 = __ldg(&bias[n0 + 1]);
            float2 v0, v1;
            v0.x = gelu_f(acc[mf][nf][0] + b0);
            v0.y = gelu_f(acc[mf][nf][1] + b1);
            v1.x = gelu_f(acc[mf][nf][2] + b0);
            v1.y = gelu_f(acc[mf][nf][3] + b1);
            *(float2*)&C[(size_t)m0 * OO + n0] = v0;
            *(float2*)&C[(size_t)(m0 + 8) * OO + n0] = v1;
        }
    }
}

// ---------------- launch ----------------
extern "C" void kernel_launch(void* const* d_in, const int* in_sizes, int n_in,
                              void* d_out, int out_size) {
    const float* x = (const float*)d_in[0];
    const float* W = (const float*)d_in[2];
    const float* b = (const float*)d_in[3];
    float* out = (float*)d_out;

    cudaFuncSetAttribute(gemm_f16_kernel,
                         cudaFuncAttributeMaxDynamicSharedMemorySize, SMEM_TOTAL);

    packw_kernel<<<(OO * KK / 8) / 256, 256>>>(W);   // 128 blocks, tiny

    dim3 grid(NN / BM, OO / BN);  // (64, 4) = 256 CTAs, 2/SM, single wave
    gemm_f16_kernel<<<grid, THREADS, SMEM_TOTAL>>>(x, b, out);
}

// round 15
// speedup vs baseline: 1.6008x; 1.6008x over previous
#include <cuda_runtime.h>
#include <cuda_fp16.h>
#include <cstdint>
#include <math.h>

// out = GELU_exact(x @ W.T + b)
// R15: fp16 single-term mma.sync GEMM, 64x64 tiles (1024 CTAs) to eliminate
// the 148-SM wave-quantization imbalance (per-SM units 6.92 -> span 7, ~1%
// loss vs 15% at 128x128). 128 thr/CTA, 4 warps (warp 32x32), occ 4,
// 3-stage cp.async ring, B-fragment double buffer, hoisted addressing.

#define NN 8192
#define KK 512
#define OO 512

#define BM 64
#define BN 64
#define BK 64                    // fp16 elems per k-tile (128 B/row)
#define NKT (KK / BK)            // 8
#define THREADS 128

#define ST_B   8192              // stage: A[64x128B] 8K | B[64x128B] 8K
#define STAGE  16384
#define NSTAGE 3
#define SMEM_TOTAL (NSTAGE * STAGE)   // 48 KB -> occ 4 = 192 KB

__device__ __align__(128) __half g_xh[NN * KK];   // 8 MB
__device__ __align__(128) __half g_wh[OO * KK];   // 0.5 MB

__device__ __forceinline__ uint32_t smem_u32(const void* p) {
    uint32_t a;
    asm("{ .reg .u64 t; cvta.to.shared.u64 t, %1; cvt.u32.u64 %0, t; }" : "=r"(a) : "l"(p));
    return a;
}

#define CP16(dst, src) \
    asm volatile("cp.async.cg.shared.global [%0], [%1], 16;" :: "r"(dst), "l"(src) : "memory")
#define CP_COMMIT() asm volatile("cp.async.commit_group;" ::: "memory")
#define CP_WAIT1()  asm volatile("cp.async.wait_group 1;" ::: "memory")

__device__ __forceinline__ void ldm4(uint32_t* r, uint32_t addr) {
    asm volatile("ldmatrix.sync.aligned.m8n8.x4.shared.b16 {%0,%1,%2,%3}, [%4];"
                 : "=r"(r[0]), "=r"(r[1]), "=r"(r[2]), "=r"(r[3]) : "r"(addr));
}

__device__ __forceinline__ void mma_f16(float* d, const uint32_t* a, const uint32_t* b) {
    asm volatile(
        "mma.sync.aligned.m16n8k16.row.col.f32.f16.f16.f32 "
        "{%0,%1,%2,%3}, {%4,%5,%6,%7}, {%8,%9}, {%0,%1,%2,%3};"
        : "+f"(d[0]), "+f"(d[1]), "+f"(d[2]), "+f"(d[3])
        : "r"(a[0]), "r"(a[1]), "r"(a[2]), "r"(a[3]), "r"(b[0]), "r"(b[1]));
}

__device__ __forceinline__ uint32_t packh2(float a, float b) {
    __half2 h = __floats2half2_rn(a, b);
    return *(uint32_t*)&h;
}

// swizzled byte offset in a 128B-row tile: row r, 16B-chunk c (0..7)
__device__ __forceinline__ uint32_t swz8(int r, int c) {
    return (uint32_t)(r * 128 + (((c ^ (r & 7))) << 4));
}

// A&S 7.1.26 erf (abs err 1.5e-7)
__device__ __forceinline__ float gelu_f(float h) {
    float s = h * 0.70710678118654752f;
    float a = fabsf(s);
    float t = __frcp_rn(fmaf(0.3275911f, a, 1.0f));
    float p = fmaf(fmaf(fmaf(fmaf(1.061405429f, t, -1.453152027f), t, 1.421413741f),
                        t, -0.284496736f), t, 0.254829592f) * t;
    float e = __expf(-a * a);
    float erfv = fmaf(-p, e, 1.0f);
    erfv = copysignf(erfv, s);
    return 0.5f * h * (1.0f + erfv);
}

// ---------------- pack kernel: f32 -> fp16 (rne), x and W ----------------
__global__ __launch_bounds__(256) void pack_kernel(const float* __restrict__ x,
                                                   const float* __restrict__ W) {
    const int g = blockIdx.x * 256 + threadIdx.x;
    const int A_GROUPS = NN * (KK / 8);
    const float* src;
    __half* dst;
    if (g < A_GROUPS) {
        src = x + (size_t)g * 8;
        dst = g_xh + (size_t)g * 8;
    } else {
        size_t g2 = (size_t)(g - A_GROUPS);
        src = W + g2 * 8;
        dst = g_wh + g2 * 8;
    }
    float4 v0 = *(const float4*)src;
    float4 v1 = *(const float4*)(src + 4);
    uint4 o;
    o.x = packh2(v0.x, v0.y);
    o.y = packh2(v0.z, v0.w);
    o.z = packh2(v1.x, v1.y);
    o.w = packh2(v1.z, v1.w);
    *(uint4*)dst = o;
}

// ---------------- main GEMM kernel ----------------
__global__ __launch_bounds__(THREADS, 4)
void gemm_f16_kernel(const float* __restrict__ bias, float* __restrict__ C) {
    extern __shared__ uint8_t smem[];
    const uint32_t S = smem_u32(smem);
    const int tid = threadIdx.x;
    const int l = tid & 31, wid = tid >> 5;
    const int mwarp = wid & 1;   // 2 M-warps of 32 rows
    const int nwarp = wid >> 1;  // 2 N-warps of 32 cols
    const int mb = blockIdx.x, nb = blockIdx.y;

    // ---- hoisted loader addressing: 64 rows x 8 chunks = 512 slots, 4/thread ----
    const int lr = tid >> 3, lc = tid & 7;       // row 0..15, chunk 0..7
    uint32_t s_dstA[4], s_dstB[4];
    const uint8_t *gA[4], *gB[4];
#pragma unroll
    for (int j = 0; j < 4; j++) {
        int r = lr + j * 16;
        s_dstA[j] = swz8(r, lc);
        s_dstB[j] = ST_B + swz8(r, lc);
        gA[j] = (const uint8_t*)(g_xh + (size_t)(mb * BM + r) * KK + lc * 8);
        gB[j] = (const uint8_t*)(g_wh + (size_t)(nb * BN + r) * KK + lc * 8);
    }

    // ---- hoisted ldmatrix bases (slice ks = base ^ ((2*ks)<<4)) ----
    const int a_r = ((l >> 3) & 1) * 8 + (l & 7);
    const int a_cs = (l >> 4) & 1;
    const int b_n = ((l >> 4) & 1) * 8 + (l & 7);
    const int b_cs = (l >> 3) & 1;
    uint32_t baseA[2], baseB[2];
#pragma unroll
    for (int mf = 0; mf < 2; mf++) baseA[mf] = swz8(mwarp * 32 + mf * 16 + a_r, a_cs);
#pragma unroll
    for (int nf2 = 0; nf2 < 2; nf2++) baseB[nf2] = ST_B + swz8(nwarp * 32 + nf2 * 16 + b_n, b_cs);

    float acc[2][4][4];
#pragma unroll
    for (int i = 0; i < 2; i++)
#pragma unroll
        for (int j = 0; j < 4; j++)
#pragma unroll
            for (int k = 0; k < 4; k++) acc[i][j][k] = 0.0f;

    // prologue: stages for kt 0,1
#pragma unroll
    for (int s = 0; s < 2; s++) {
        const uint32_t st = S + s * STAGE;
#pragma unroll
        for (int j = 0; j < 4; j++) {
            CP16(st + s_dstA[j], gA[j] + s * 128);
            CP16(st + s_dstB[j], gB[j] + s * 128);
        }
        CP_COMMIT();
    }

    for (int kt = 0; kt < NKT; kt++) {
        CP_WAIT1();
        __syncthreads();
        if (kt + 2 < NKT) {
            const uint32_t st = S + ((kt + 2) % NSTAGE) * STAGE;
            const uint32_t go = (uint32_t)(kt + 2) * 128;
#pragma unroll
            for (int j = 0; j < 4; j++) {
                CP16(st + s_dstA[j], gA[j] + go);
                CP16(st + s_dstB[j], gB[j] + go);
            }
            CP_COMMIT();
        }
        const uint32_t stg = S + (kt % NSTAGE) * STAGE;

        // B-fragment double buffer across the 4 k16 slices; A inline
        uint32_t Bf[2][8];
#pragma unroll
        for (int nf2 = 0; nf2 < 2; nf2++)
            ldm4(&Bf[0][nf2 * 4], stg + baseB[nf2]);

#pragma unroll
        for (int ks = 0; ks < 4; ks++) {
            const int cur = ks & 1, nxt = cur ^ 1;
            if (ks < 3) {
                const uint32_t nko = (uint32_t)(2 * (ks + 1)) << 4;
#pragma unroll
                for (int nf2 = 0; nf2 < 2; nf2++)
                    ldm4(&Bf[nxt][nf2 * 4], stg + (baseB[nf2] ^ nko));
            }
            const uint32_t ksoff = (uint32_t)(2 * ks) << 4;
#pragma unroll
            for (int mf = 0; mf < 2; mf++) {
                uint32_t A[4];
                ldm4(A, stg + (baseA[mf] ^ ksoff));
#pragma unroll
                for (int nf = 0; nf < 4; nf++)
                    mma_f16(acc[mf][nf], A, &Bf[cur][nf * 2]);
            }
        }
    }

    // epilogue: bias + GELU
#pragma unroll
    for (int mf = 0; mf < 2; mf++) {
#pragma unroll
        for (int nf = 0; nf < 4; nf++) {
            int m0 = mb * BM + mwarp * 32 + mf * 16 + (l >> 2);
            int n0 = nb * BN + nwarp * 32 + nf * 8 + 2 * (l & 3);
            float b0 = __ldg(&bias[n0]);
            float b1 = __ldg(&bias[n0 + 1]);
            float2 v0, v1;
            v0.x = gelu_f(acc[mf][nf][0] + b0);
            v0.y = gelu_f(acc[mf][nf][1] + b1);
            v1.x = gelu_f(acc[mf][nf][2] + b0);
            v1.y = gelu_f(acc[mf][nf][3] + b1);
            *(float2*)&C[(size_t)m0 * OO + n0] = v0;
            *(float2*)&C[(size_t)(m0 + 8) * OO + n0] = v1;
        }
    }
}

// ---------------- launch ----------------
extern "C" void kernel_launch(void* const* d_in, const int* in_sizes, int n_in,
                              void* d_out, int out_size) {
    const float* x = (const float*)d_in[0];
    const float* W = (const float*)d_in[2];
    const float* b = (const float*)d_in[3];
    float* out = (float*)d_out;

    cudaFuncSetAttribute(gemm_f16_kernel,
                         cudaFuncAttributeMaxDynamicSharedMemorySize, SMEM_TOTAL);

    const int A_GROUPS = NN * (KK / 8);
    const int B_GROUPS = OO * (KK / 8);
    pack_kernel<<<(A_GROUPS + B_GROUPS) / 256, 256>>>(x, W);

    dim3 grid(NN / BM, OO / BN);  // (128, 8) = 1024 CTAs, occ 4
    gemm_f16_kernel<<<grid, THREADS, SMEM_TOTAL>>>(b, out);
}